// round 9
// baseline (speedup 1.0000x reference)
#include <cuda_runtime.h>
#include <cuda_fp16.h>
#include <cstdint>

// ===================== problem constants =====================
#define M_TOTAL 8192
#define N_TOTAL 4096
#define K_TOTAL 4096

#define BM 128
#define BN 256
#define BK 128
#define STAGES 2
#define NUM_KC (K_TOTAL / BK)   // 32
#define NTHREADS 256

#define ROW_BYTES 256                    // BK=128 halves per row
#define A_BYTES (BM * ROW_BYTES)         // 32768
#define B_BYTES (BN * ROW_BYTES)         // 65536
#define STAGE_BYTES (A_BYTES + B_BYTES)  // 98304
#define SMEM_TOTAL (STAGES * STAGE_BYTES) // 196608

// ===================== device scratch =====================
__device__ __half W_g[(size_t)N_TOTAL * K_TOTAL];  // 32 MB, [N,K] K-major
__device__ __half X_g[(size_t)M_TOTAL * K_TOTAL];  // 64 MB, [M,K] K-major

// ===================== helpers =====================
#define DEVFN __device__ __forceinline__

DEVFN uint32_t smem_u32(const void* p) {
    uint32_t a;
    asm("{ .reg .u64 t; cvta.to.shared.u64 t, %1; cvt.u32.u64 %0, t; }" : "=r"(a) : "l"(p));
    return a;
}

DEVFN void cp_async16(uint32_t dst, const void* src) {
    asm volatile("cp.async.cg.shared.global [%0], [%1], 16;\n" :: "r"(dst), "l"(src));
}
DEVFN void cp_commit() { asm volatile("cp.async.commit_group;\n" ::: "memory"); }
template <int N> DEVFN void cp_wait() { asm volatile("cp.async.wait_group %0;\n" :: "n"(N) : "memory"); }

// 256B-row swizzle: XOR row bits [0:3) (offset bits 8-10) into 16B-chunk bits (offset bits 4-6)
#define SWZ(o) ((o) ^ (((o) >> 4) & 0x70))

DEVFN void ldsm4(uint32_t* r, uint32_t addr) {
    asm volatile("ldmatrix.sync.aligned.m8n8.x4.shared.b16 {%0,%1,%2,%3}, [%4];"
                 : "=r"(r[0]), "=r"(r[1]), "=r"(r[2]), "=r"(r[3]) : "r"(addr));
}

// Not volatile — pure register op; lets ptxas interleave HMMA with LDSM.
DEVFN void mma16816(float* d, const uint32_t* a, const uint32_t* b) {
    asm("mma.sync.aligned.m16n8k16.row.col.f32.f16.f16.f32 "
        "{%0,%1,%2,%3}, {%4,%5,%6,%7}, {%8,%9}, {%0,%1,%2,%3};"
        : "+f"(d[0]), "+f"(d[1]), "+f"(d[2]), "+f"(d[3])
        : "r"(a[0]), "r"(a[1]), "r"(a[2]), "r"(a[3]), "r"(b[0]), "r"(b[1]));
}

// ===================== fused prep: dequant W + convert X =====================
// E2M1 magnitudes * 2 = {0,1,2,3,4,6,8,12} packed as nibbles of 0xC8643210.
DEVFN __half2 dec2(int b, float hs) {  // hs = 0.5f * scale
    int ch = (b >> 4) & 7, sh = (b >> 7) & 1;   // high nibble -> even element
    int cl = b & 7,        sl = (b >> 3) & 1;   // low nibble  -> odd element
    float mh = (float)((0xC8643210u >> (ch * 4)) & 0xF);
    float ml = (float)((0xC8643210u >> (cl * 4)) & 0xF);
    float fh = mh * (sh ? -hs : hs);
    float fl = ml * (sl ? -hs : hs);
    return make_half2(__float2half_rn(fh), __float2half_rn(fl));
}

#define W_BLOCKS (N_TOTAL * K_TOTAL / 2 / 4 / 256)   // 8192
#define X_BLOCKS (M_TOTAL * K_TOTAL / 8 / 256)       // 16384

__global__ void __launch_bounds__(256)
prep_kernel(const int* __restrict__ wp, const float* __restrict__ ws,
            const float* __restrict__ x) {
    const int bid = blockIdx.x;
    if (bid < W_BLOCKS) {
        int i = bid * 256 + threadIdx.x;             // byte group [4i, 4i+4)
        int4 p = reinterpret_cast<const int4*>(wp)[i];
        float hs = __ldg(ws + (i >> 1)) * 0.5f;      // 8 values share one 16-block scale
        union { __half2 h[4]; uint4 u; } o;
        o.h[0] = dec2(p.x & 255, hs);
        o.h[1] = dec2(p.y & 255, hs);
        o.h[2] = dec2(p.z & 255, hs);
        o.h[3] = dec2(p.w & 255, hs);
        reinterpret_cast<uint4*>(W_g)[i] = o.u;
    } else {
        int i = (bid - W_BLOCKS) * 256 + threadIdx.x;  // float group [8i, 8i+8)
        float4 v0 = reinterpret_cast<const float4*>(x)[2 * i];
        float4 v1 = reinterpret_cast<const float4*>(x)[2 * i + 1];
        union { __half2 h[4]; uint4 u; } r;
        r.h[0] = make_half2(__float2half_rn(v0.x), __float2half_rn(v0.y));
        r.h[1] = make_half2(__float2half_rn(v0.z), __float2half_rn(v0.w));
        r.h[2] = make_half2(__float2half_rn(v1.x), __float2half_rn(v1.y));
        r.h[3] = make_half2(__float2half_rn(v1.z), __float2half_rn(v1.w));
        reinterpret_cast<uint4*>(X_g)[i] = r.u;
    }
}

// ===================== HMMA GEMM =====================
// Load one half (8 x 16B chunks per row) of one BK=128 stage.
// half 0 = k[0:64), half 1 = k[64:128). 3072 cp.asyncs, 12 per thread.
DEVFN void load_half(uint32_t a_sm, uint32_t b_sm,
                     const __half* __restrict__ Ag, const __half* __restrict__ Bg,
                     int kc, int half, int tid) {
    const int kbyte = kc * ROW_BYTES + half * 128;
#pragma unroll
    for (int t = tid; t < (BM + BN) * 8; t += NTHREADS) {
        int row, chunk;
        uint32_t base;
        const __half* g;
        if (t < BM * 8) { row = t >> 3; chunk = t & 7; base = a_sm; g = Ag + (size_t)row * K_TOTAL; }
        else { int u = t - BM * 8; row = u >> 3; chunk = u & 7; base = b_sm; g = Bg + (size_t)row * K_TOTAL; }
        uint32_t off = SWZ((uint32_t)(row * ROW_BYTES + (half * 8 + chunk) * 16));
        cp_async16(base + off, (const char*)g + kbyte + chunk * 16);
    }
}

__global__ void __launch_bounds__(NTHREADS, 1)
gemm_kernel(const float* __restrict__ bias, float* __restrict__ out) {
    extern __shared__ char smem[];
    const uint32_t sb = smem_u32(smem);
    const int tid = threadIdx.x;
    const int wid = tid >> 5;
    const int lane = tid & 31;
    const int m0 = blockIdx.y * BM;
    const int n0 = blockIdx.x * BN;
    const __half* Ag = X_g + (size_t)m0 * K_TOTAL;
    const __half* Bg = W_g + (size_t)n0 * K_TOTAL;

    // warp tile: 64x64. warp_m in {0,1}, warp_n in {0..3}
    const int warp_m = wid & 1;
    const int warp_n = wid >> 1;

    float acc[4][8][4];
#pragma unroll
    for (int i = 0; i < 4; i++)
#pragma unroll
        for (int j = 0; j < 8; j++)
#pragma unroll
            for (int k = 0; k < 4; k++) acc[i][j][k] = 0.f;

    // intra-tile ldmatrix offsets (bytes, pre-swizzle). chunk = 2*ks + {0,1}, ks in 0..7
    const int a_row = warp_m * 64 + (lane & 15);
    const int a_ch  = lane >> 4;
    const int b_row = warp_n * 64 + ((lane >> 4) & 1) * 8 + (lane & 7);
    const int b_ch  = (lane >> 3) & 1;

    uint32_t afr[2][4][4];
    uint32_t bfr[2][8][2];

#define LD_AFRAGS(buf, base, ks_) do { \
    _Pragma("unroll") \
    for (int mt = 0; mt < 4; mt++) { \
        uint32_t off = (uint32_t)((a_row + mt * 16) * ROW_BYTES + (2 * (ks_) + a_ch) * 16); \
        ldsm4(afr[buf][mt], (base) + SWZ(off)); \
    } } while (0)

#define LD_BFRAGS(buf, base, ks_) do { \
    _Pragma("unroll") \
    for (int ng = 0; ng < 4; ng++) { \
        uint32_t r_[4]; \
        uint32_t off = (uint32_t)((b_row + ng * 16) * ROW_BYTES + (2 * (ks_) + b_ch) * 16); \
        ldsm4(r_, (base) + SWZ(off)); \
        bfr[buf][2 * ng][0] = r_[0]; bfr[buf][2 * ng][1] = r_[1]; \
        bfr[buf][2 * ng + 1][0] = r_[2]; bfr[buf][2 * ng + 1][1] = r_[3]; \
    } } while (0)

#define MMA_BATCH(buf) do { \
    _Pragma("unroll") \
    for (int mt = 0; mt < 4; mt++) \
        _Pragma("unroll") \
        for (int nt = 0; nt < 8; nt++) \
            mma16816(acc[mt][nt], afr[buf][mt], bfr[buf][nt]); \
    } while (0)

    // prologue: issue stage 0 (H0, H1 as separate groups); wait H0; warm ks0 frags
    load_half(sb, sb + A_BYTES, Ag, Bg, 0, 0, tid);
    cp_commit();
    load_half(sb, sb + A_BYTES, Ag, Bg, 0, 1, tid);
    cp_commit();
    cp_wait<1>();
    __syncthreads();
    LD_AFRAGS(0, sb, 0);
    LD_BFRAGS(0, sb + A_BYTES, 0);

    for (int kc = 0; kc < NUM_KC; kc++) {
        const uint32_t abase = sb + (uint32_t)(kc & 1) * STAGE_BYTES;
        const uint32_t bbase = abase + A_BYTES;
        const uint32_t anext = sb + (uint32_t)((kc + 1) & 1) * STAGE_BYTES;
        const uint32_t bnext = anext + A_BYTES;

        // ks0: issue next stage (two groups; empty commits on last iter keep counts aligned)
        if (kc + 1 < NUM_KC) {
            load_half(anext, bnext, Ag, Bg, kc + 1, 0, tid);
            cp_commit();
            load_half(anext, bnext, Ag, Bg, kc + 1, 1, tid);
            cp_commit();
        } else {
            cp_commit();
            cp_commit();
        }
        LD_AFRAGS(1, abase, 1);  LD_BFRAGS(1, bbase, 1);  MMA_BATCH(0);
        // ks1
        LD_AFRAGS(0, abase, 2);  LD_BFRAGS(0, bbase, 2);  MMA_BATCH(1);
        // ks2
        LD_AFRAGS(1, abase, 3);  LD_BFRAGS(1, bbase, 3);  MMA_BATCH(0);
        // ks3: own-stage H1 must be resident for ks4 frags (retires group kc.H1)
        cp_wait<2>();
        LD_AFRAGS(0, abase, 4);  LD_BFRAGS(0, bbase, 4);  MMA_BATCH(1);
        // ks4
        LD_AFRAGS(1, abase, 5);  LD_BFRAGS(1, bbase, 5);  MMA_BATCH(0);
        // ks5
        LD_AFRAGS(0, abase, 6);  LD_BFRAGS(0, bbase, 6);  MMA_BATCH(1);
        // ks6: last reads of stage kc, then wait next-stage H0 + the ONLY barrier
        LD_AFRAGS(1, abase, 7);  LD_BFRAGS(1, bbase, 7);
        cp_wait<1>();
        __syncthreads();
        MMA_BATCH(0);
        // ks7: prefetch next stage's ks0 frags under the MMAs
        if (kc + 1 < NUM_KC) {
            LD_AFRAGS(0, anext, 0);
            LD_BFRAGS(0, bnext, 0);
        }
        MMA_BATCH(1);
    }

    // ===================== epilogue =====================
    const int mrow = m0 + warp_m * 64 + (lane >> 2);
    const int ncol = n0 + warp_n * 64 + (lane & 3) * 2;

    float2 bv[8];
#pragma unroll
    for (int nt = 0; nt < 8; nt++) {
        bv[nt].x = __ldg(bias + ncol + nt * 8);
        bv[nt].y = __ldg(bias + ncol + nt * 8 + 1);
    }

#pragma unroll
    for (int mt = 0; mt < 4; mt++) {
        float* r0 = out + (size_t)(mrow + mt * 16) * N_TOTAL + ncol;
        float* r1 = r0 + 8 * N_TOTAL;
#pragma unroll
        for (int nt = 0; nt < 8; nt++) {
            float2 v0 = make_float2(acc[mt][nt][0] + bv[nt].x, acc[mt][nt][1] + bv[nt].y);
            float2 v1 = make_float2(acc[mt][nt][2] + bv[nt].x, acc[mt][nt][3] + bv[nt].y);
            *reinterpret_cast<float2*>(r0 + nt * 8) = v0;
            *reinterpret_cast<float2*>(r1 + nt * 8) = v1;
        }
    }
}

// ===================== launch =====================
extern "C" void kernel_launch(void* const* d_in, const int* in_sizes, int n_in,
                              void* d_out, int out_size) {
    const float* x    = (const float*)d_in[0];
    const int*   wp   = (const int*)d_in[1];
    const float* ws   = (const float*)d_in[2];
    const float* bias = (const float*)d_in[3];
    float* out = (float*)d_out;

    cudaFuncSetAttribute(gemm_kernel, cudaFuncAttributeMaxDynamicSharedMemorySize, SMEM_TOTAL);

    prep_kernel<<<W_BLOCKS + X_BLOCKS, 256>>>(wp, ws, x);

    dim3 grid(N_TOTAL / BN, M_TOTAL / BM);  // (16, 64)
    gemm_kernel<<<grid, NTHREADS, SMEM_TOTAL>>>(bias, out);
}

// round 10
// speedup vs baseline: 1.0985x; 1.0985x over previous
#include <cuda_runtime.h>
#include <cuda_fp16.h>
#include <cstdint>

// ===================== problem constants =====================
#define M_TOTAL 8192
#define N_TOTAL 4096
#define K_TOTAL 4096

#define BM 128
#define BN 256
#define BK 64
#define STAGES 3
#define NUM_KC (K_TOTAL / BK)   // 64
#define NTHREADS 256

#define A_BYTES (BM * 128)               // 16384 (BK=64 halves = 128B per row)
#define B_BYTES (BN * 128)               // 32768
#define STAGE_BYTES (A_BYTES + B_BYTES)  // 49152
#define SMEM_TOTAL (STAGES * STAGE_BYTES) // 147456

// ===================== device scratch =====================
__device__ __half W_g[(size_t)N_TOTAL * K_TOTAL];  // 32 MB, [N,K] K-major
__device__ __half X_g[(size_t)M_TOTAL * K_TOTAL];  // 64 MB, [M,K] K-major

// ===================== helpers =====================
#define DEVFN __device__ __forceinline__

DEVFN uint32_t smem_u32(const void* p) {
    uint32_t a;
    asm("{ .reg .u64 t; cvta.to.shared.u64 t, %1; cvt.u32.u64 %0, t; }" : "=r"(a) : "l"(p));
    return a;
}

DEVFN void cp_async16(uint32_t dst, const void* src) {
    asm volatile("cp.async.cg.shared.global [%0], [%1], 16;\n" :: "r"(dst), "l"(src));
}
DEVFN void cp_commit() { asm volatile("cp.async.commit_group;\n" ::: "memory"); }
template <int N> DEVFN void cp_wait() { asm volatile("cp.async.wait_group %0;\n" :: "n"(N) : "memory"); }

// split rendezvous: 256 threads arrive + 256 threads sync = 512
#define BAR_ARRIVE() asm volatile("bar.arrive 1, 512;" ::: "memory")
#define BAR_WAIT()   asm volatile("bar.sync 1, 512;" ::: "memory")

#define SW128(o) ((o) ^ (((o) >> 3) & 0x70))

DEVFN void ldsm4(uint32_t* r, uint32_t addr) {
    asm volatile("ldmatrix.sync.aligned.m8n8.x4.shared.b16 {%0,%1,%2,%3}, [%4];"
                 : "=r"(r[0]), "=r"(r[1]), "=r"(r[2]), "=r"(r[3]) : "r"(addr));
}

// Not volatile — pure register op; lets ptxas interleave HMMA with LDSM.
DEVFN void mma16816(float* d, const uint32_t* a, const uint32_t* b) {
    asm("mma.sync.aligned.m16n8k16.row.col.f32.f16.f16.f32 "
        "{%0,%1,%2,%3}, {%4,%5,%6,%7}, {%8,%9}, {%0,%1,%2,%3};"
        : "+f"(d[0]), "+f"(d[1]), "+f"(d[2]), "+f"(d[3])
        : "r"(a[0]), "r"(a[1]), "r"(a[2]), "r"(a[3]), "r"(b[0]), "r"(b[1]));
}

// ===================== fused prep: dequant W + convert X =====================
// E2M1 magnitudes * 2 = {0,1,2,3,4,6,8,12} packed as nibbles of 0xC8643210.
DEVFN __half2 dec2(int b, float hs) {  // hs = 0.5f * scale
    int ch = (b >> 4) & 7, sh = (b >> 7) & 1;   // high nibble -> even element
    int cl = b & 7,        sl = (b >> 3) & 1;   // low nibble  -> odd element
    float mh = (float)((0xC8643210u >> (ch * 4)) & 0xF);
    float ml = (float)((0xC8643210u >> (cl * 4)) & 0xF);
    float fh = mh * (sh ? -hs : hs);
    float fl = ml * (sl ? -hs : hs);
    return make_half2(__float2half_rn(fh), __float2half_rn(fl));
}

#define W_BLOCKS (N_TOTAL * K_TOTAL / 2 / 4 / 256)   // 8192
#define X_BLOCKS (M_TOTAL * K_TOTAL / 8 / 256)       // 16384

__global__ void __launch_bounds__(256)
prep_kernel(const int* __restrict__ wp, const float* __restrict__ ws,
            const float* __restrict__ x) {
    const int bid = blockIdx.x;
    if (bid < W_BLOCKS) {
        int i = bid * 256 + threadIdx.x;             // byte group [4i, 4i+4)
        int4 p = reinterpret_cast<const int4*>(wp)[i];
        float hs = __ldg(ws + (i >> 1)) * 0.5f;      // 8 values share one 16-block scale
        union { __half2 h[4]; uint4 u; } o;
        o.h[0] = dec2(p.x & 255, hs);
        o.h[1] = dec2(p.y & 255, hs);
        o.h[2] = dec2(p.z & 255, hs);
        o.h[3] = dec2(p.w & 255, hs);
        reinterpret_cast<uint4*>(W_g)[i] = o.u;
    } else {
        int i = (bid - W_BLOCKS) * 256 + threadIdx.x;  // float group [8i, 8i+8)
        float4 v0 = reinterpret_cast<const float4*>(x)[2 * i];
        float4 v1 = reinterpret_cast<const float4*>(x)[2 * i + 1];
        union { __half2 h[4]; uint4 u; } r;
        r.h[0] = make_half2(__float2half_rn(v0.x), __float2half_rn(v0.y));
        r.h[1] = make_half2(__float2half_rn(v0.z), __float2half_rn(v0.w));
        r.h[2] = make_half2(__float2half_rn(v1.x), __float2half_rn(v1.y));
        r.h[3] = make_half2(__float2half_rn(v1.z), __float2half_rn(v1.w));
        reinterpret_cast<uint4*>(X_g)[i] = r.u;
    }
}

// ===================== HMMA GEMM =====================
DEVFN void load_chunk(uint32_t a_sm, uint32_t b_sm,
                      const __half* __restrict__ Ag, const __half* __restrict__ Bg,
                      int kc, int tid) {
    const int kbyte = kc * (BK * 2);
#pragma unroll
    for (int t = tid; t < (BM + BN) * 8; t += NTHREADS) {
        int row, chunk;
        uint32_t base;
        const __half* g;
        if (t < BM * 8) { row = t >> 3; chunk = t & 7; base = a_sm; g = Ag + (size_t)row * K_TOTAL; }
        else { int u = t - BM * 8; row = u >> 3; chunk = u & 7; base = b_sm; g = Bg + (size_t)row * K_TOTAL; }
        uint32_t off = SW128((uint32_t)(row * 128 + chunk * 16));
        cp_async16(base + off, (const char*)g + kbyte + chunk * 16);
    }
}

__global__ void __launch_bounds__(NTHREADS, 1)
gemm_kernel(const float* __restrict__ bias, float* __restrict__ out) {
    extern __shared__ char smem[];
    const uint32_t sb = smem_u32(smem);
    const int tid = threadIdx.x;
    const int wid = tid >> 5;
    const int lane = tid & 31;
    const int m0 = blockIdx.y * BM;
    const int n0 = blockIdx.x * BN;
    const __half* Ag = X_g + (size_t)m0 * K_TOTAL;
    const __half* Bg = W_g + (size_t)n0 * K_TOTAL;

    // warp tile: 64x64. warp_m in {0,1}, warp_n in {0..3}
    const int warp_m = wid & 1;
    const int warp_n = wid >> 1;

    float acc[4][8][4];
#pragma unroll
    for (int i = 0; i < 4; i++)
#pragma unroll
        for (int j = 0; j < 8; j++)
#pragma unroll
            for (int k = 0; k < 4; k++) acc[i][j][k] = 0.f;

    // intra-tile ldmatrix offsets (bytes, pre-swizzle)
    const int a_row = warp_m * 64 + (lane & 15);
    const int a_ch  = lane >> 4;
    const int b_row = warp_n * 64 + ((lane >> 4) & 1) * 8 + (lane & 7);
    const int b_ch  = (lane >> 3) & 1;

    uint32_t afr[2][4][4];
    uint32_t bfr[2][8][2];

#define LD_AFRAGS(buf, base, ks_) do { \
    _Pragma("unroll") \
    for (int mt = 0; mt < 4; mt++) { \
        uint32_t off = (uint32_t)((a_row + mt * 16) * 128 + (2 * (ks_) + a_ch) * 16); \
        ldsm4(afr[buf][mt], (base) + SW128(off)); \
    } } while (0)

#define LD_BFRAGS(buf, base, ks_) do { \
    _Pragma("unroll") \
    for (int ng = 0; ng < 4; ng++) { \
        uint32_t r_[4]; \
        uint32_t off = (uint32_t)((b_row + ng * 16) * 128 + (2 * (ks_) + b_ch) * 16); \
        ldsm4(r_, (base) + SW128(off)); \
        bfr[buf][2 * ng][0] = r_[0]; bfr[buf][2 * ng][1] = r_[1]; \
        bfr[buf][2 * ng + 1][0] = r_[2]; bfr[buf][2 * ng + 1][1] = r_[3]; \
    } } while (0)

#define MMA_BATCH(buf) do { \
    _Pragma("unroll") \
    for (int mt = 0; mt < 4; mt++) \
        _Pragma("unroll") \
        for (int nt = 0; nt < 8; nt++) \
            mma16816(acc[mt][nt], afr[buf][mt], bfr[buf][nt]); \
    } while (0)

    // prologue: issue stages 0,1; wait stage 0; prefetch ks=0 frags
#pragma unroll
    for (int j = 0; j < STAGES - 1; j++) {
        uint32_t ab = sb + j * STAGE_BYTES;
        load_chunk(ab, ab + A_BYTES, Ag, Bg, j, tid);
        cp_commit();
    }
    cp_wait<STAGES - 2>();
    __syncthreads();
    {
        LD_AFRAGS(0, sb, 0);
        LD_BFRAGS(0, sb + A_BYTES, 0);
    }

    for (int kc = 0; kc < NUM_KC; kc++) {
        const uint32_t abase = sb + (uint32_t)(kc % STAGES) * STAGE_BYTES;
        const uint32_t bbase = abase + A_BYTES;
        const uint32_t anext = sb + (uint32_t)((kc + 1) % STAGES) * STAGE_BYTES;
        const uint32_t bnext = anext + A_BYTES;

        // ks = 0: issue gmem loads for stage kc+2 (slot freed by prev-iter bar.sync)
        {
            const int jl = kc + STAGES - 1;
            if (jl < NUM_KC) {
                uint32_t ab = sb + (uint32_t)(jl % STAGES) * STAGE_BYTES;
                load_chunk(ab, ab + A_BYTES, Ag, Bg, jl, tid);
            }
            cp_commit();
            LD_AFRAGS(1, abase, 1);
            LD_BFRAGS(1, bbase, 1);
            MMA_BATCH(0);
        }
        // ks = 1
        {
            LD_AFRAGS(0, abase, 2);
            LD_BFRAGS(0, bbase, 2);
            MMA_BATCH(1);
        }
        // ks = 2: last smem read of stage kc -> own cp_wait -> ARRIVE (no stall), then MMAs
        {
            LD_AFRAGS(1, abase, 3);
            LD_BFRAGS(1, bbase, 3);
            cp_wait<STAGES - 2>();
            BAR_ARRIVE();
            MMA_BATCH(0);
        }
        // ks = 3: WAIT (all arrived => stage kc+1 visible, stage kc fully read), prefetch next
        {
            BAR_WAIT();
            if (kc + 1 < NUM_KC) {
                LD_AFRAGS(0, anext, 0);
                LD_BFRAGS(0, bnext, 0);
            }
            MMA_BATCH(1);
        }
    }

    // ===================== epilogue =====================
    const int mrow = m0 + warp_m * 64 + (lane >> 2);
    const int ncol = n0 + warp_n * 64 + (lane & 3) * 2;

    float2 bv[8];
#pragma unroll
    for (int nt = 0; nt < 8; nt++) {
        bv[nt].x = __ldg(bias + ncol + nt * 8);
        bv[nt].y = __ldg(bias + ncol + nt * 8 + 1);
    }

#pragma unroll
    for (int mt = 0; mt < 4; mt++) {
        float* r0 = out + (size_t)(mrow + mt * 16) * N_TOTAL + ncol;
        float* r1 = r0 + 8 * N_TOTAL;
#pragma unroll
        for (int nt = 0; nt < 8; nt++) {
            float2 v0 = make_float2(acc[mt][nt][0] + bv[nt].x, acc[mt][nt][1] + bv[nt].y);
            float2 v1 = make_float2(acc[mt][nt][2] + bv[nt].x, acc[mt][nt][3] + bv[nt].y);
            *reinterpret_cast<float2*>(r0 + nt * 8) = v0;
            *reinterpret_cast<float2*>(r1 + nt * 8) = v1;
        }
    }
}

// ===================== launch =====================
extern "C" void kernel_launch(void* const* d_in, const int* in_sizes, int n_in,
                              void* d_out, int out_size) {
    const float* x    = (const float*)d_in[0];
    const int*   wp   = (const int*)d_in[1];
    const float* ws   = (const float*)d_in[2];
    const float* bias = (const float*)d_in[3];
    float* out = (float*)d_out;

    cudaFuncSetAttribute(gemm_kernel, cudaFuncAttributeMaxDynamicSharedMemorySize, SMEM_TOTAL);

    prep_kernel<<<W_BLOCKS + X_BLOCKS, 256>>>(wp, ws, x);

    dim3 grid(N_TOTAL / BN, M_TOTAL / BM);  // (16, 64)
    gemm_kernel<<<grid, NTHREADS, SMEM_TOTAL>>>(bias, out);
}